// round 2
// baseline (speedup 1.0000x reference)
#include <cuda_runtime.h>
#include <math.h>
#include <float.h>

#define BATCH 2
#define SEQ   8192
#define DIM   1024
#define HEADS 8
#define DH    64
#define HDH   512
#define WIN   64
#define NWIN  128
#define NQ    1024
#define NKV   2048
#define NITER 50
#define NTOK  (BATCH*SEQ)
#define NKEY  (NKV+1)

// ---------------- scratch (static device globals; no runtime allocation) ----------------
__device__ float g_xn[(size_t)NTOK*DIM];
__device__ float g_rms[NTOK];
__device__ float g_s[2][NTOK];
__device__ float g_qkv[(size_t)NTOK*(3*HDH)];
__device__ float g_lo[(size_t)NTOK*HDH];
__device__ int   g_iq[BATCH][NQ];
__device__ float g_sq[BATCH][NQ];
__device__ int   g_ikv[BATCH][NKV];
__device__ float g_skv[BATCH][NKV];
__device__ int   g_qpos[NTOK];
__device__ float g_xqn[(size_t)BATCH*NQ*DIM];
__device__ float g_xkvn[(size_t)BATCH*NKV*DIM];
__device__ float g_qh[(size_t)BATCH*NQ*HDH];
__device__ float g_kvh[(size_t)BATCH*NKV*DIM];
__device__ float g_kh[(size_t)BATCH*HEADS*NKEY*DH];
__device__ float g_vh[(size_t)BATCH*HEADS*NKEY*DH];
__device__ float g_ho[(size_t)BATCH*NQ*HDH];
__device__ float g_routed[(size_t)BATCH*NQ*DIM];

// ---------------- block reductions ----------------
__device__ __forceinline__ float bsum256(float v, float* sh) {
    int lane = threadIdx.x & 31, w = threadIdx.x >> 5;
    #pragma unroll
    for (int o = 16; o; o >>= 1) v += __shfl_xor_sync(0xffffffffu, v, o);
    __syncthreads();
    if (lane == 0) sh[w] = v;
    __syncthreads();
    float r = sh[0];
    #pragma unroll
    for (int i = 1; i < 8; i++) r += sh[i];
    return r;
}

__device__ __forceinline__ float bsum1024(float v, float* sh) {
    int lane = threadIdx.x & 31, w = threadIdx.x >> 5;
    #pragma unroll
    for (int o = 16; o; o >>= 1) v += __shfl_xor_sync(0xffffffffu, v, o);
    __syncthreads();
    if (lane == 0) sh[w] = v;
    __syncthreads();
    float r = sh[0];
    #pragma unroll
    for (int i = 1; i < 32; i++) r += sh[i];
    return r;
}

__device__ __forceinline__ float bmax1024(float v, float* sh) {
    int lane = threadIdx.x & 31, w = threadIdx.x >> 5;
    #pragma unroll
    for (int o = 16; o; o >>= 1) v = fmaxf(v, __shfl_xor_sync(0xffffffffu, v, o));
    __syncthreads();
    if (lane == 0) sh[w] = v;
    __syncthreads();
    float r = sh[0];
    #pragma unroll
    for (int i = 1; i < 32; i++) r = fmaxf(r, sh[i]);
    return r;
}

// ---------------- 1. layernorm + routing dots + rms scale ----------------
__global__ __launch_bounds__(256) void k_ln(const float* __restrict__ x,
        const float* __restrict__ ln_g, const float* __restrict__ ln_b,
        const float* __restrict__ rt_q, const float* __restrict__ rt_kv) {
    __shared__ float sh[32];
    __shared__ float s_mean, s_inv;
    int row = blockIdx.x;
    const float* xr = x + (size_t)row * DIM;
    int tid = threadIdx.x;
    float v[4], s = 0.f, ss = 0.f, dq = 0.f, dk = 0.f;
    #pragma unroll
    for (int u = 0; u < 4; u++) {
        int i = tid + 256 * u;
        float t = xr[i];
        v[u] = t; s += t; ss += t * t; dq += t * rt_q[i]; dk += t * rt_kv[i];
    }
    s  = bsum256(s, sh);
    ss = bsum256(ss, sh);
    dq = bsum256(dq, sh);
    dk = bsum256(dk, sh);
    if (tid == 0) {
        float mean = s * (1.0f / DIM);
        float var  = ss * (1.0f / DIM) - mean * mean;
        s_mean = mean;
        s_inv  = 1.0f / sqrtf(var + 1e-5f);
        g_rms[row] = 32.0f / fmaxf(sqrtf(ss), 1e-12f);   // sqrt(DIM)=32
        g_s[0][row] = dq;
        g_s[1][row] = dk;
    }
    __syncthreads();
    float mean = s_mean, inv = s_inv;
    #pragma unroll
    for (int u = 0; u < 4; u++) {
        int i = tid + 256 * u;
        g_xn[(size_t)row * DIM + i] = (v[u] - mean) * inv * ln_g[i] + ln_b[i];
    }
}

// ---------------- 2. qpos init ----------------
__global__ void k_init() {
    int i = blockIdx.x * blockDim.x + threadIdx.x;
    if (i < NTOK) g_qpos[i] = -1;
}

// ---------------- 3. coor_descent + exact-tie-break top-k (bitonic) ----------------
__global__ __launch_bounds__(1024) void k_route() {
    extern __shared__ unsigned long long keys[];   // SEQ * 8 bytes
    __shared__ float sh[32];
    int tid = threadIdx.x;
    int b = blockIdx.x >> 1, route = blockIdx.x & 1;
    const float* sp = g_s[route] + b * SEQ;
    float s[8], bb[8];
    #pragma unroll
    for (int u = 0; u < 8; u++) { s[u] = sp[tid + 1024 * u]; bb[u] = -s[u]; }
    float logk = logf(route ? 2304.0f : 1152.0f);   // min(N*9/8, SEQ)
    float a = 0.0f;
    for (int it = 0; it < NITER; it++) {
        float lm = -FLT_MAX;
        #pragma unroll
        for (int u = 0; u < 8; u++) lm = fmaxf(lm, s[u] + bb[u]);
        float m = bmax1024(lm, sh);
        float ls = 0.0f;
        #pragma unroll
        for (int u = 0; u < 8; u++) ls += expf(s[u] + bb[u] - m);
        float sum = bsum1024(ls, sh);
        a = logk - (logf(sum) + m);                 // EPS = 1
        #pragma unroll
        for (int u = 0; u < 8; u++) bb[u] = -fmaxf(s[u] + a, 0.0f);
    }
    #pragma unroll
    for (int u = 0; u < 8; u++) {
        int idx = tid + 1024 * u;
        float sc = expf(s[u] + a + bb[u]);          // exactly 1.0 when s+a>0
        keys[idx] = ((unsigned long long)__float_as_uint(sc) << 32)
                  | (unsigned)(SEQ - 1 - idx);      // tie: lower idx wins
    }
    __syncthreads();
    // bitonic sort, descending
    for (int k2 = 2; k2 <= SEQ; k2 <<= 1) {
        for (int j = k2 >> 1; j > 0; j >>= 1) {
            #pragma unroll
            for (int w = 0; w < 8; w++) {
                int i = tid + 1024 * w;
                int ixj = i ^ j;
                if (ixj > i) {
                    unsigned long long A = keys[i], B = keys[ixj];
                    bool sw = ((i & k2) == 0) ? (A < B) : (A > B);
                    if (sw) { keys[i] = B; keys[ixj] = A; }
                }
            }
            __syncthreads();
        }
    }
    int N = route ? NKV : NQ;
    for (int i = tid; i < N; i += 1024) {
        unsigned long long kk = keys[i];
        int idx = (SEQ - 1) - (int)(unsigned)(kk & 0xffffffffu);
        float sc = __uint_as_float((unsigned)(kk >> 32));
        float sel = sc + (1.0f - sc);               // straight-through value
        if (route) { g_ikv[b][i] = idx; g_skv[b][i] = sel; }
        else       { g_iq[b][i] = idx;  g_sq[b][i] = sel; g_qpos[b * SEQ + idx] = i; }
    }
}

// ---------------- 4. gather + rmsnorm ----------------
__global__ __launch_bounds__(256) void k_gather(const float* __restrict__ x,
                                                const float* __restrict__ rms_g) {
    int r = blockIdx.x, tid = threadIdx.x;
    int b, tok; float* dst;
    if (r < BATCH * NQ) { b = r / NQ; tok = g_iq[b][r % NQ]; dst = g_xqn + (size_t)r * DIM; }
    else { int r2 = r - BATCH * NQ; b = r2 / NKV; tok = g_ikv[b][r2 % NKV]; dst = g_xkvn + (size_t)r2 * DIM; }
    const float* src = x + ((size_t)(b * SEQ) + tok) * DIM;
    float sc = g_rms[b * SEQ + tok];
    for (int i = tid; i < DIM; i += 256) dst[i] = src[i] * sc * rms_g[i];
}

// ---------------- 5. SGEMM: C[M,N] = A[M,K] * B[K,N], all row-major, dims %128/%16 ----------------
__global__ __launch_bounds__(256) void k_sgemm(const float* __restrict__ A,
        const float* __restrict__ B, float* __restrict__ C, int M, int N, int K) {
    __shared__ float As[16][128];
    __shared__ float Bs[16][128];
    int tid = threadIdx.x;
    const float* Ab = A + (size_t)(blockIdx.y * 128) * K;
    const float* Bb = B + blockIdx.x * 128;
    float acc[8][8];
    #pragma unroll
    for (int m = 0; m < 8; m++)
        #pragma unroll
        for (int n = 0; n < 8; n++) acc[m][n] = 0.0f;
    int ty = (tid >> 4) << 3, tx = (tid & 15) << 3;
    for (int k0 = 0; k0 < K; k0 += 16) {
        #pragma unroll
        for (int i = 0; i < 2; i++) {
            int id = tid + 256 * i;
            int ar = id >> 2, ac = (id & 3) << 2;
            float4 av = *(const float4*)(Ab + (size_t)ar * K + k0 + ac);
            As[ac][ar] = av.x; As[ac + 1][ar] = av.y; As[ac + 2][ar] = av.z; As[ac + 3][ar] = av.w;
            int br = id >> 5, bc = (id & 31) << 2;
            *(float4*)&Bs[br][bc] = *(const float4*)(Bb + (size_t)(k0 + br) * N + bc);
        }
        __syncthreads();
        #pragma unroll
        for (int kk = 0; kk < 16; kk++) {
            float ra[8], rb[8];
            #pragma unroll
            for (int m = 0; m < 8; m++) ra[m] = As[kk][ty + m];
            #pragma unroll
            for (int n = 0; n < 8; n++) rb[n] = Bs[kk][tx + n];
            #pragma unroll
            for (int m = 0; m < 8; m++)
                #pragma unroll
                for (int n = 0; n < 8; n++) acc[m][n] += ra[m] * rb[n];
        }
        __syncthreads();
    }
    #pragma unroll
    for (int m = 0; m < 8; m++) {
        float* cr = C + (size_t)(blockIdx.y * 128 + ty + m) * N + blockIdx.x * 128 + tx;
        *(float4*)cr       = make_float4(acc[m][0], acc[m][1], acc[m][2], acc[m][3]);
        *(float4*)(cr + 4) = make_float4(acc[m][4], acc[m][5], acc[m][6], acc[m][7]);
    }
}

// ---------------- 6. light (windowed) attention ----------------
__global__ __launch_bounds__(64) void k_lattn() {
    __shared__ float ks[WIN][DH], vs[WIN][DH];
    int idx = blockIdx.x;
    int w = idx & (NWIN - 1), h = (idx >> 7) & 7, b = idx >> 10;
    int tid = threadIdx.x;
    const float* qrow = g_qkv + ((size_t)(b * SEQ + w * WIN + tid)) * (3 * HDH) + h * DH;
    float q[DH];
    #pragma unroll
    for (int d = 0; d < DH; d++) q[d] = qrow[d] * 0.125f;   // DH^-0.5
    float m = -FLT_MAX, l = 0.0f, o[DH];
    #pragma unroll
    for (int d = 0; d < DH; d++) o[d] = 0.0f;
    for (int kw = w - 1; kw <= w + 1; kw++) {
        if (kw < 0 || kw >= NWIN) continue;
        __syncthreads();
        const float* kbase = g_qkv + ((size_t)(b * SEQ + kw * WIN)) * (3 * HDH) + HDH + h * DH;
        for (int f = tid; f < WIN * 16; f += 64) {
            int rj = f >> 4, c4 = (f & 15) << 2;
            const float* rp = kbase + (size_t)rj * (3 * HDH);
            *(float4*)&ks[rj][c4] = *(const float4*)(rp + c4);
            *(float4*)&vs[rj][c4] = *(const float4*)(rp + HDH + c4);
        }
        __syncthreads();
        for (int j = 0; j < WIN; j++) {
            float s0 = 0.f, s1 = 0.f, s2 = 0.f, s3 = 0.f;
            #pragma unroll
            for (int d = 0; d < DH; d += 4) {
                s0 += q[d] * ks[j][d];     s1 += q[d + 1] * ks[j][d + 1];
                s2 += q[d + 2] * ks[j][d + 2]; s3 += q[d + 3] * ks[j][d + 3];
            }
            float sim = (s0 + s1) + (s2 + s3);
            if (sim > m) {
                float rs = expf(m - sim);
                l *= rs;
                #pragma unroll
                for (int d = 0; d < DH; d++) o[d] *= rs;
                m = sim;
            }
            float p = expf(sim - m);
            l += p;
            #pragma unroll
            for (int d = 0; d < DH; d++) o[d] += p * vs[j][d];
        }
    }
    float inv = 1.0f / l;
    float* dst = g_lo + ((size_t)(b * SEQ + w * WIN + tid)) * HDH + h * DH;
    #pragma unroll
    for (int d = 0; d < DH; d++) dst[d] = o[d] * inv;
}

// ---------------- 7. build heavy K/V (null-prepend + score scale) ----------------
__global__ void k_kvprep(const float* __restrict__ null_kv) {
    const int total = BATCH * HEADS * NKEY * DH;
    for (int i = blockIdx.x * blockDim.x + threadIdx.x; i < total; i += gridDim.x * blockDim.x) {
        int d = i & (DH - 1);
        int j = (i / DH) % NKEY;
        int h = (i / (DH * NKEY)) % HEADS;
        int b = i / (DH * NKEY * HEADS);
        float kv, vv;
        if (j == 0) {
            kv = null_kv[h * DH + d];
            vv = null_kv[HEADS * DH + h * DH + d];
        } else {
            size_t rowo = ((size_t)(b * NKV + j - 1)) * DIM + h * 2 * DH;
            kv = g_kvh[rowo + d];
            vv = g_kvh[rowo + DH + d] * g_skv[b][j - 1];
        }
        g_kh[i] = kv;
        g_vh[i] = vv;
    }
}

// ---------------- 8. heavy attention ----------------
__global__ __launch_bounds__(64) void k_hattn() {
    __shared__ float ks[64][DH], vs[64][DH];
    int idx = blockIdx.x;
    int qb = idx & 15, h = (idx >> 4) & 7, b = idx >> 7;
    int tid = threadIdx.x;
    int qi = qb * 64 + tid;
    const float* qrow = g_qh + ((size_t)(b * NQ + qi)) * HDH + h * DH;
    float q[DH];
    #pragma unroll
    for (int d = 0; d < DH; d++) q[d] = qrow[d] * 0.125f;
    float m = -FLT_MAX, l = 0.0f, o[DH];
    #pragma unroll
    for (int d = 0; d < DH; d++) o[d] = 0.0f;
    const float* kb = g_kh + ((size_t)(b * HEADS + h)) * NKEY * DH;
    const float* vb = g_vh + ((size_t)(b * HEADS + h)) * NKEY * DH;
    for (int c0 = 0; c0 < NKEY; c0 += 64) {
        int cnt = min(64, NKEY - c0);
        __syncthreads();
        for (int f = tid; f < cnt * 16; f += 64) {
            int rj = f >> 4, c4 = (f & 15) << 2;
            *(float4*)&ks[rj][c4] = *(const float4*)(kb + (size_t)(c0 + rj) * DH + c4);
            *(float4*)&vs[rj][c4] = *(const float4*)(vb + (size_t)(c0 + rj) * DH + c4);
        }
        __syncthreads();
        for (int j = 0; j < cnt; j++) {
            float s0 = 0.f, s1 = 0.f, s2 = 0.f, s3 = 0.f;
            #pragma unroll
            for (int d = 0; d < DH; d += 4) {
                s0 += q[d] * ks[j][d];         s1 += q[d + 1] * ks[j][d + 1];
                s2 += q[d + 2] * ks[j][d + 2]; s3 += q[d + 3] * ks[j][d + 3];
            }
            float sim = (s0 + s1) + (s2 + s3);
            if (sim > m) {
                float rs = expf(m - sim);
                l *= rs;
                #pragma unroll
                for (int d = 0; d < DH; d++) o[d] *= rs;
                m = sim;
            }
            float p = expf(sim - m);
            l += p;
            #pragma unroll
            for (int d = 0; d < DH; d++) o[d] += p * vs[j][d];
        }
    }
    float inv = 1.0f / l;
    float* dst = g_ho + ((size_t)(b * NQ + qi)) * HDH + h * DH;
    #pragma unroll
    for (int d = 0; d < DH; d++) dst[d] = o[d] * inv;
}

// ---------------- 9. combine: out = light + (routed*sq | null_q) ----------------
__global__ __launch_bounds__(256) void k_combine(float* __restrict__ out,
                                                 const float* __restrict__ null_q) {
    int row = blockIdx.x, tid = threadIdx.x;
    int pos = g_qpos[row];
    float* orow = out + (size_t)row * DIM;
    if (pos >= 0) {
        int b = row / SEQ;
        float sq = g_sq[b][pos];
        const float* rr = g_routed + ((size_t)(b * NQ + pos)) * DIM;
        for (int i = tid; i < DIM; i += 256) orow[i] += rr[i] * sq;
    } else {
        for (int i = tid; i < DIM; i += 256) orow[i] += null_q[i];
    }
}

// ---------------- launcher ----------------
extern "C" void kernel_launch(void* const* d_in, const int* in_sizes, int n_in,
                              void* d_out, int out_size) {
    const float* x       = (const float*)d_in[0];
    const float* ln_g    = (const float*)d_in[1];
    const float* ln_b    = (const float*)d_in[2];
    const float* w_qkv_l = (const float*)d_in[3];
    const float* w_out_l = (const float*)d_in[4];
    const float* null_q  = (const float*)d_in[5];
    const float* rt_q    = (const float*)d_in[6];
    const float* rt_kv   = (const float*)d_in[7];
    const float* rms_g   = (const float*)d_in[8];
    const float* w_q_h   = (const float*)d_in[9];
    const float* w_kv_h  = (const float*)d_in[10];
    const float* null_kv = (const float*)d_in[11];
    const float* w_out_h = (const float*)d_in[12];
    float* out = (float*)d_out;

    void *p_xn, *p_qkv, *p_lo, *p_xqn, *p_xkvn, *p_qh, *p_kvh, *p_ho, *p_routed;
    cudaGetSymbolAddress(&p_xn, g_xn);
    cudaGetSymbolAddress(&p_qkv, g_qkv);
    cudaGetSymbolAddress(&p_lo, g_lo);
    cudaGetSymbolAddress(&p_xqn, g_xqn);
    cudaGetSymbolAddress(&p_xkvn, g_xkvn);
    cudaGetSymbolAddress(&p_qh, g_qh);
    cudaGetSymbolAddress(&p_kvh, g_kvh);
    cudaGetSymbolAddress(&p_ho, g_ho);
    cudaGetSymbolAddress(&p_routed, g_routed);

    cudaFuncSetAttribute(k_route, cudaFuncAttributeMaxDynamicSharedMemorySize, SEQ * 8);

    k_ln<<<NTOK, 256>>>(x, ln_g, ln_b, rt_q, rt_kv);
    k_init<<<(NTOK + 255) / 256, 256>>>();
    k_route<<<4, 1024, SEQ * 8>>>();
    k_gather<<<BATCH * (NQ + NKV), 256>>>(x, rms_g);

    // light path
    k_sgemm<<<dim3((3 * HDH) / 128, NTOK / 128), 256>>>((const float*)p_xn, w_qkv_l, (float*)p_qkv, NTOK, 3 * HDH, DIM);
    k_lattn<<<BATCH * HEADS * NWIN, 64>>>();
    k_sgemm<<<dim3(DIM / 128, NTOK / 128), 256>>>((const float*)p_lo, w_out_l, out, NTOK, DIM, HDH);

    // heavy path
    k_sgemm<<<dim3(HDH / 128, (BATCH * NQ) / 128), 256>>>((const float*)p_xqn, w_q_h, (float*)p_qh, BATCH * NQ, HDH, DIM);
    k_sgemm<<<dim3(DIM / 128, (BATCH * NKV) / 128), 256>>>((const float*)p_xkvn, w_kv_h, (float*)p_kvh, BATCH * NKV, DIM, DIM);
    k_kvprep<<<1024, 256>>>(null_kv);
    k_hattn<<<BATCH * HEADS * (NQ / 64), 64>>>();
    k_sgemm<<<dim3(DIM / 128, (BATCH * NQ) / 128), 256>>>((const float*)p_ho, w_out_h, (float*)p_routed, BATCH * NQ, DIM, HDH);

    k_combine<<<NTOK, 256>>>(out, null_q);
}

// round 4
// speedup vs baseline: 2.2392x; 2.2392x over previous
#include <cuda_runtime.h>
#include <cuda_fp16.h>
#include <stdint.h>
#include <math.h>
#include <float.h>

#define BATCH 2
#define SEQ   8192
#define DIM   1024
#define HEADS 8
#define DH    64
#define HDH   512
#define WIN   64
#define NWIN  128
#define NQ    1024
#define NKV   2048
#define NITER 50
#define NTOK  (BATCH*SEQ)
#define NKEY  (NKV+1)

// ---------------- scratch ----------------
__device__ __half g_xnh[(size_t)NTOK*DIM];
__device__ float g_rms[NTOK];
__device__ float g_s[2][NTOK];
__device__ float g_qkv[(size_t)NTOK*(3*HDH)];
__device__ __half g_loh[(size_t)NTOK*HDH];
__device__ int   g_iq[BATCH][NQ];
__device__ float g_sq[BATCH][NQ];
__device__ int   g_ikv[BATCH][NKV];
__device__ float g_skv[BATCH][NKV];
__device__ int   g_qpos[NTOK];
__device__ __half g_xqnh[(size_t)BATCH*NQ*DIM];
__device__ __half g_xkvnh[(size_t)BATCH*NKV*DIM];
__device__ float g_qh[(size_t)BATCH*NQ*HDH];
__device__ float g_kvh[(size_t)BATCH*NKV*DIM];
__device__ float g_kh[(size_t)BATCH*HEADS*NKEY*DH];
__device__ float g_vh[(size_t)BATCH*HEADS*NKEY*DH];
__device__ __half g_hoh[(size_t)BATCH*NQ*HDH];
__device__ float g_routed[(size_t)BATCH*NQ*DIM];
// fp16 weights
__device__ __half g_wqkvh[(size_t)DIM*3*HDH];
__device__ __half g_wolh[(size_t)HDH*DIM];
__device__ __half g_wqh[(size_t)DIM*HDH];
__device__ __half g_wkvh[(size_t)DIM*DIM];
__device__ __half g_wohh[(size_t)HDH*DIM];

// ---------------- helpers ----------------
__device__ __forceinline__ unsigned saddr(const void* p) {
    return (unsigned)__cvta_generic_to_shared(p);
}
__device__ __forceinline__ void cp16(unsigned dst, const void* src) {
    asm volatile("cp.async.cg.shared.global [%0], [%1], 16;" :: "r"(dst), "l"(src));
}
__device__ __forceinline__ void ldsm_x4(unsigned* r, unsigned a) {
    asm volatile("ldmatrix.sync.aligned.m8n8.x4.shared.b16 {%0,%1,%2,%3}, [%4];"
        : "=r"(r[0]), "=r"(r[1]), "=r"(r[2]), "=r"(r[3]) : "r"(a));
}
__device__ __forceinline__ void ldsm_x2t(unsigned* r, unsigned a) {
    asm volatile("ldmatrix.sync.aligned.m8n8.x2.trans.shared.b16 {%0,%1}, [%2];"
        : "=r"(r[0]), "=r"(r[1]) : "r"(a));
}
__device__ __forceinline__ void mma16816(float* d, const unsigned* a, const unsigned* b) {
    asm volatile("mma.sync.aligned.m16n8k16.row.col.f32.f16.f16.f32 "
        "{%0,%1,%2,%3}, {%4,%5,%6,%7}, {%8,%9}, {%0,%1,%2,%3};"
        : "+f"(d[0]), "+f"(d[1]), "+f"(d[2]), "+f"(d[3])
        : "r"(a[0]), "r"(a[1]), "r"(a[2]), "r"(a[3]), "r"(b[0]), "r"(b[1]));
}

__device__ __forceinline__ float bsum256(float v, float* sh) {
    int lane = threadIdx.x & 31, w = threadIdx.x >> 5;
    #pragma unroll
    for (int o = 16; o; o >>= 1) v += __shfl_xor_sync(0xffffffffu, v, o);
    __syncthreads();
    if (lane == 0) sh[w] = v;
    __syncthreads();
    float r = sh[0];
    #pragma unroll
    for (int i = 1; i < 8; i++) r += sh[i];
    return r;
}
__device__ __forceinline__ float bsum1024(float v, float* sh) {
    int lane = threadIdx.x & 31, w = threadIdx.x >> 5;
    #pragma unroll
    for (int o = 16; o; o >>= 1) v += __shfl_xor_sync(0xffffffffu, v, o);
    __syncthreads();
    if (lane == 0) sh[w] = v;
    __syncthreads();
    float r = sh[0];
    #pragma unroll
    for (int i = 1; i < 32; i++) r += sh[i];
    return r;
}
__device__ __forceinline__ float bmax1024(float v, float* sh) {
    int lane = threadIdx.x & 31, w = threadIdx.x >> 5;
    #pragma unroll
    for (int o = 16; o; o >>= 1) v = fmaxf(v, __shfl_xor_sync(0xffffffffu, v, o));
    __syncthreads();
    if (lane == 0) sh[w] = v;
    __syncthreads();
    float r = sh[0];
    #pragma unroll
    for (int i = 1; i < 32; i++) r = fmaxf(r, sh[i]);
    return r;
}

// ---------------- 1. layernorm + routing dots ----------------
__global__ __launch_bounds__(256) void k_ln(const float* __restrict__ x,
        const float* __restrict__ ln_g, const float* __restrict__ ln_b,
        const float* __restrict__ rt_q, const float* __restrict__ rt_kv) {
    __shared__ float sh[32];
    __shared__ float s_mean, s_inv;
    int row = blockIdx.x;
    const float* xr = x + (size_t)row * DIM;
    int tid = threadIdx.x;
    float v[4], s = 0.f, ss = 0.f, dq = 0.f, dk = 0.f;
    #pragma unroll
    for (int u = 0; u < 4; u++) {
        int i = tid + 256 * u;
        float t = xr[i];
        v[u] = t; s += t; ss += t * t; dq += t * rt_q[i]; dk += t * rt_kv[i];
    }
    s  = bsum256(s, sh);
    ss = bsum256(ss, sh);
    dq = bsum256(dq, sh);
    dk = bsum256(dk, sh);
    if (tid == 0) {
        float mean = s * (1.0f / DIM);
        float var  = ss * (1.0f / DIM) - mean * mean;
        s_mean = mean;
        s_inv  = 1.0f / sqrtf(var + 1e-5f);
        g_rms[row] = 32.0f / fmaxf(sqrtf(ss), 1e-12f);
        g_s[0][row] = dq;
        g_s[1][row] = dk;
    }
    __syncthreads();
    float mean = s_mean, inv = s_inv;
    #pragma unroll
    for (int u = 0; u < 4; u++) {
        int i = tid + 256 * u;
        g_xnh[(size_t)row * DIM + i] = __float2half((v[u] - mean) * inv * ln_g[i] + ln_b[i]);
    }
}

// ---------------- 2. qpos init ----------------
__global__ void k_init() {
    int i = blockIdx.x * blockDim.x + threadIdx.x;
    if (i < NTOK) g_qpos[i] = -1;
}

// ---------------- 3. f32 -> f16 weight convert ----------------
__global__ void k_f2h(const float* __restrict__ s, __half* __restrict__ d, int n) {
    for (int i = blockIdx.x * blockDim.x + threadIdx.x; i < n; i += gridDim.x * blockDim.x)
        d[i] = __float2half(s[i]);
}

// ---------------- 4. coor_descent + exact-tie-break top-k (bitonic) ----------------
__global__ __launch_bounds__(1024) void k_route() {
    extern __shared__ unsigned long long keys[];
    __shared__ float sh[32];
    int tid = threadIdx.x;
    int b = blockIdx.x >> 1, route = blockIdx.x & 1;
    const float* sp = g_s[route] + b * SEQ;
    float s[8], bb[8];
    #pragma unroll
    for (int u = 0; u < 8; u++) { s[u] = sp[tid + 1024 * u]; bb[u] = -s[u]; }
    float logk = logf(route ? 2304.0f : 1152.0f);
    float a = 0.0f;
    for (int it = 0; it < NITER; it++) {
        float lm = -FLT_MAX;
        #pragma unroll
        for (int u = 0; u < 8; u++) lm = fmaxf(lm, s[u] + bb[u]);
        float m = bmax1024(lm, sh);
        float ls = 0.0f;
        #pragma unroll
        for (int u = 0; u < 8; u++) ls += expf(s[u] + bb[u] - m);
        float sum = bsum1024(ls, sh);
        a = logk - (logf(sum) + m);
        #pragma unroll
        for (int u = 0; u < 8; u++) bb[u] = -fmaxf(s[u] + a, 0.0f);
    }
    #pragma unroll
    for (int u = 0; u < 8; u++) {
        int idx = tid + 1024 * u;
        float sc = expf(s[u] + a + bb[u]);
        keys[idx] = ((unsigned long long)__float_as_uint(sc) << 32)
                  | (unsigned)(SEQ - 1 - idx);
    }
    __syncthreads();
    for (int k2 = 2; k2 <= SEQ; k2 <<= 1) {
        for (int j = k2 >> 1; j > 0; j >>= 1) {
            #pragma unroll
            for (int w = 0; w < 8; w++) {
                int i = tid + 1024 * w;
                int ixj = i ^ j;
                if (ixj > i) {
                    unsigned long long A = keys[i], B = keys[ixj];
                    bool sw = ((i & k2) == 0) ? (A < B) : (A > B);
                    if (sw) { keys[i] = B; keys[ixj] = A; }
                }
            }
            __syncthreads();
        }
    }
    int N = route ? NKV : NQ;
    for (int i = tid; i < N; i += 1024) {
        unsigned long long kk = keys[i];
        int idx = (SEQ - 1) - (int)(unsigned)(kk & 0xffffffffu);
        float sc = __uint_as_float((unsigned)(kk >> 32));
        float sel = sc + (1.0f - sc);
        if (route) { g_ikv[b][i] = idx; g_skv[b][i] = sel; }
        else       { g_iq[b][i] = idx;  g_sq[b][i] = sel; g_qpos[b * SEQ + idx] = i; }
    }
}

// ---------------- 5. gather + rmsnorm (fp16 out) ----------------
__global__ __launch_bounds__(256) void k_gather(const float* __restrict__ x,
                                                const float* __restrict__ rms_g) {
    int r = blockIdx.x, tid = threadIdx.x;
    int b, tok; __half* dst;
    if (r < BATCH * NQ) { b = r / NQ; tok = g_iq[b][r % NQ]; dst = g_xqnh + (size_t)r * DIM; }
    else { int r2 = r - BATCH * NQ; b = r2 / NKV; tok = g_ikv[b][r2 % NKV]; dst = g_xkvnh + (size_t)r2 * DIM; }
    const float* src = x + ((size_t)(b * SEQ) + tok) * DIM;
    float sc = g_rms[b * SEQ + tok];
    for (int i = tid; i < DIM; i += 256) dst[i] = __float2half(src[i] * sc * rms_g[i]);
}

// ---------------- 6. fp16 tensor-core GEMM: C[M,N] = A[M,K]*B[K,N] ----------------
// 128x128x32 tile, 8 warps (2x4), warp tile 64x32, double-buffered cp.async
__global__ __launch_bounds__(256) void k_hgemm(const __half* __restrict__ A,
        const __half* __restrict__ B, float* __restrict__ C, int M, int N, int K) {
    __shared__ __half As[2][128 * 40];   // row stride 40 halfs (80B)
    __shared__ __half Bs[2][32 * 136];   // row stride 136 halfs (272B)
    int tid = threadIdx.x, lane = tid & 31, wid = tid >> 5;
    int wm = (wid & 1) * 64, wn = (wid >> 1) * 32;
    int arow = tid >> 2, acol = (tid & 3) * 8;
    int brow = tid >> 4, bcol = (tid & 15) * 8;
    const __half* Ag = A + (size_t)(blockIdx.y * 128) * K;
    const __half* Bg = B + blockIdx.x * 128;
    float acc[4][4][4];
    #pragma unroll
    for (int mt = 0; mt < 4; mt++)
        #pragma unroll
        for (int nt = 0; nt < 4; nt++)
            #pragma unroll
            for (int i = 0; i < 4; i++) acc[mt][nt][i] = 0.0f;

    {   // prologue: stage 0
        const __half* a0 = Ag + (size_t)arow * K + acol;
        cp16(saddr(&As[0][arow * 40 + acol]), a0);
        cp16(saddr(&As[0][(arow + 64) * 40 + acol]), a0 + (size_t)64 * K);
        const __half* b0 = Bg + (size_t)brow * N + bcol;
        cp16(saddr(&Bs[0][brow * 136 + bcol]), b0);
        cp16(saddr(&Bs[0][(brow + 16) * 136 + bcol]), b0 + (size_t)16 * N);
        asm volatile("cp.async.commit_group;");
    }
    int nstage = K >> 5;
    for (int s = 0; s < nstage; s++) {
        asm volatile("cp.async.wait_group 0;");
        __syncthreads();
        if (s + 1 < nstage) {
            int k0 = (s + 1) << 5;
            int st = (s + 1) & 1;
            const __half* a0 = Ag + (size_t)arow * K + k0 + acol;
            cp16(saddr(&As[st][arow * 40 + acol]), a0);
            cp16(saddr(&As[st][(arow + 64) * 40 + acol]), a0 + (size_t)64 * K);
            const __half* b0 = Bg + (size_t)(k0 + brow) * N + bcol;
            cp16(saddr(&Bs[st][brow * 136 + bcol]), b0);
            cp16(saddr(&Bs[st][(brow + 16) * 136 + bcol]), b0 + (size_t)16 * N);
            asm volatile("cp.async.commit_group;");
        }
        int cur = s & 1;
        #pragma unroll
        for (int kk = 0; kk < 32; kk += 16) {
            unsigned af[4][4], bf[4][2];
            #pragma unroll
            for (int mt = 0; mt < 4; mt++) {
                int row = wm + mt * 16 + (lane & 15);
                int col = kk + (lane >> 4) * 8;
                ldsm_x4(af[mt], saddr(&As[cur][row * 40 + col]));
            }
            #pragma unroll
            for (int nt = 0; nt < 4; nt++) {
                int row = kk + (lane & 15);
                ldsm_x2t(bf[nt], saddr(&Bs[cur][row * 136 + wn + nt * 8]));
            }
            #pragma unroll
            for (int mt = 0; mt < 4; mt++)
                #pragma unroll
                for (int nt = 0; nt < 4; nt++)
                    mma16816(acc[mt][nt], af[mt], bf[nt]);
        }
    }
    #pragma unroll
    for (int mt = 0; mt < 4; mt++) {
        int r = blockIdx.y * 128 + wm + mt * 16 + (lane >> 2);
        #pragma unroll
        for (int nt = 0; nt < 4; nt++) {
            int c = blockIdx.x * 128 + wn + nt * 8 + (lane & 3) * 2;
            *(float2*)(C + (size_t)r * N + c)       = make_float2(acc[mt][nt][0], acc[mt][nt][1]);
            *(float2*)(C + (size_t)(r + 8) * N + c) = make_float2(acc[mt][nt][2], acc[mt][nt][3]);
        }
    }
}

// ---------------- 7. light (windowed) attention ----------------
__global__ __launch_bounds__(64) void k_lattn() {
    __shared__ float ks[WIN][DH], vs[WIN][DH];
    int idx = blockIdx.x;
    int w = idx & (NWIN - 1), h = (idx >> 7) & 7, b = idx >> 10;
    int tid = threadIdx.x;
    const float* qrow = g_qkv + ((size_t)(b * SEQ + w * WIN + tid)) * (3 * HDH) + h * DH;
    float q[DH];
    #pragma unroll
    for (int d = 0; d < DH; d++) q[d] = qrow[d] * 0.125f;
    float m = -FLT_MAX, l = 0.0f, o[DH];
    #pragma unroll
    for (int d = 0; d < DH; d++) o[d] = 0.0f;
    for (int kw = w - 1; kw <= w + 1; kw++) {
        if (kw < 0 || kw >= NWIN) continue;
        __syncthreads();
        const float* kbase = g_qkv + ((size_t)(b * SEQ + kw * WIN)) * (3 * HDH) + HDH + h * DH;
        for (int f = tid; f < WIN * 16; f += 64) {
            int rj = f >> 4, c4 = (f & 15) << 2;
            const float* rp = kbase + (size_t)rj * (3 * HDH);
            *(float4*)&ks[rj][c4] = *(const float4*)(rp + c4);
            *(float4*)&vs[rj][c4] = *(const float4*)(rp + HDH + c4);
        }
        __syncthreads();
        for (int j = 0; j < WIN; j++) {
            float s0 = 0.f, s1 = 0.f, s2 = 0.f, s3 = 0.f;
            #pragma unroll
            for (int d = 0; d < DH; d += 4) {
                float4 k4 = *(const float4*)&ks[j][d];
                s0 += q[d] * k4.x;     s1 += q[d + 1] * k4.y;
                s2 += q[d + 2] * k4.z; s3 += q[d + 3] * k4.w;
            }
            float sim = (s0 + s1) + (s2 + s3);
            if (sim > m) {
                float rs = expf(m - sim);
                l *= rs;
                #pragma unroll
                for (int d = 0; d < DH; d++) o[d] *= rs;
                m = sim;
            }
            float p = expf(sim - m);
            l += p;
            #pragma unroll
            for (int d = 0; d < DH; d += 4) {
                float4 v4 = *(const float4*)&vs[j][d];
                o[d] += p * v4.x;     o[d + 1] += p * v4.y;
                o[d + 2] += p * v4.z; o[d + 3] += p * v4.w;
            }
        }
    }
    float inv = 1.0f / l;
    __half* dst = g_loh + ((size_t)(b * SEQ + w * WIN + tid)) * HDH + h * DH;
    #pragma unroll
    for (int d = 0; d < DH; d += 2)
        *(__half2*)&dst[d] = __floats2half2_rn(o[d] * inv, o[d + 1] * inv);
}

// ---------------- 8. build heavy K/V ----------------
__global__ void k_kvprep(const float* __restrict__ null_kv) {
    const int total = BATCH * HEADS * NKEY * DH;
    for (int i = blockIdx.x * blockDim.x + threadIdx.x; i < total; i += gridDim.x * blockDim.x) {
        int d = i & (DH - 1);
        int j = (i / DH) % NKEY;
        int h = (i / (DH * NKEY)) % HEADS;
        int b = i / (DH * NKEY * HEADS);
        float kv, vv;
        if (j == 0) {
            kv = null_kv[h * DH + d];
            vv = null_kv[HEADS * DH + h * DH + d];
        } else {
            size_t rowo = ((size_t)(b * NKV + j - 1)) * DIM + h * 2 * DH;
            kv = g_kvh[rowo + d];
            vv = g_kvh[rowo + DH + d] * g_skv[b][j - 1];
        }
        g_kh[i] = kv;
        g_vh[i] = vv;
    }
}

// ---------------- 9. heavy attention ----------------
__global__ __launch_bounds__(64) void k_hattn() {
    __shared__ float ks[64][DH], vs[64][DH];
    int idx = blockIdx.x;
    int qb = idx & 15, h = (idx >> 4) & 7, b = idx >> 7;
    int tid = threadIdx.x;
    int qi = qb * 64 + tid;
    const float* qrow = g_qh + ((size_t)(b * NQ + qi)) * HDH + h * DH;
    float q[DH];
    #pragma unroll
    for (int d = 0; d < DH; d++) q[d] = qrow[d] * 0.125f;
    float m = -FLT_MAX, l = 0.0f, o[DH];
    #pragma unroll
    for (int d = 0; d < DH; d++) o[d] = 0.0f;
    const float* kb = g_kh + ((size_t)(b * HEADS + h)) * NKEY * DH;
    const float* vb = g_vh + ((size_t)(b * HEADS + h)) * NKEY * DH;
    for (int c0 = 0; c0 < NKEY; c0 += 64) {
        int cnt = min(64, NKEY - c0);
        __syncthreads();
        for (int f = tid; f < cnt * 16; f += 64) {
            int rj = f >> 4, c4 = (f & 15) << 2;
            *(float4*)&ks[rj][c4] = *(const float4*)(kb + (size_t)(c0 + rj) * DH + c4);
            *(float4*)&vs[rj][c4] = *(const float4*)(vb + (size_t)(c0 + rj) * DH + c4);
        }
        __syncthreads();
        for (int j = 0; j < cnt; j++) {
            float s0 = 0.f, s1 = 0.f, s2 = 0.f, s3 = 0.f;
            #pragma unroll
            for (int d = 0; d < DH; d += 4) {
                float4 k4 = *(const float4*)&ks[j][d];
                s0 += q[d] * k4.x;     s1 += q[d + 1] * k4.y;
                s2 += q[d + 2] * k4.z; s3 += q[d + 3] * k4.w;
            }
            float sim = (s0 + s1) + (s2 + s3);
            if (sim > m) {
                float rs = expf(m - sim);
                l *= rs;
                #pragma unroll
                for (int d = 0; d < DH; d++) o[d] *= rs;
                m = sim;
            }
            float p = expf(sim - m);
            l += p;
            #pragma unroll
            for (int d = 0; d < DH; d += 4) {
                float4 v4 = *(const float4*)&vs[j][d];
                o[d] += p * v4.x;     o[d + 1] += p * v4.y;
                o[d + 2] += p * v4.z; o[d + 3] += p * v4.w;
            }
        }
    }
    float inv = 1.0f / l;
    __half* dst = g_hoh + ((size_t)(b * NQ + qi)) * HDH + h * DH;
    #pragma unroll
    for (int d = 0; d < DH; d += 2)
        *(__half2*)&dst[d] = __floats2half2_rn(o[d] * inv, o[d + 1] * inv);
}

// ---------------- 10. combine ----------------
__global__ __launch_bounds__(256) void k_combine(float* __restrict__ out,
                                                 const float* __restrict__ null_q) {
    int row = blockIdx.x, tid = threadIdx.x;
    int pos = g_qpos[row];
    float* orow = out + (size_t)row * DIM;
    if (pos >= 0) {
        int b = row / SEQ;
        float sq = g_sq[b][pos];
        const float* rr = g_routed + ((size_t)(b * NQ + pos)) * DIM;
        for (int i = tid; i < DIM; i += 256) orow[i] += rr[i] * sq;
    } else {
        for (int i = tid; i < DIM; i += 256) orow[i] += null_q[i];
    }
}

// ---------------- launcher ----------------
extern "C" void kernel_launch(void* const* d_in, const int* in_sizes, int n_in,
                              void* d_out, int out_size) {
    const float* x       = (const float*)d_in[0];
    const float* ln_g    = (const float*)d_in[1];
    const float* ln_b    = (const float*)d_in[2];
    const float* w_qkv_l = (const float*)d_in[3];
    const float* w_out_l = (const float*)d_in[4];
    const float* null_q  = (const float*)d_in[5];
    const float* rt_q    = (const float*)d_in[6];
    const float* rt_kv   = (const float*)d_in[7];
    const float* rms_g   = (const float*)d_in[8];
    const float* w_q_h   = (const float*)d_in[9];
    const float* w_kv_h  = (const float*)d_in[10];
    const float* null_kv = (const float*)d_in[11];
    const float* w_out_h = (const float*)d_in[12];
    float* out = (float*)d_out;

    void *p_xnh, *p_qkv, *p_loh, *p_xqnh, *p_xkvnh, *p_qh, *p_kvh, *p_hoh, *p_routed;
    void *p_wqkvh, *p_wolh, *p_wqh, *p_wkvh, *p_wohh;
    cudaGetSymbolAddress(&p_xnh, g_xnh);
    cudaGetSymbolAddress(&p_qkv, g_qkv);
    cudaGetSymbolAddress(&p_loh, g_loh);
    cudaGetSymbolAddress(&p_xqnh, g_xqnh);
    cudaGetSymbolAddress(&p_xkvnh, g_xkvnh);
    cudaGetSymbolAddress(&p_qh, g_qh);
    cudaGetSymbolAddress(&p_kvh, g_kvh);
    cudaGetSymbolAddress(&p_hoh, g_hoh);
    cudaGetSymbolAddress(&p_routed, g_routed);
    cudaGetSymbolAddress(&p_wqkvh, g_wqkvh);
    cudaGetSymbolAddress(&p_wolh, g_wolh);
    cudaGetSymbolAddress(&p_wqh, g_wqh);
    cudaGetSymbolAddress(&p_wkvh, g_wkvh);
    cudaGetSymbolAddress(&p_wohh, g_wohh);

    cudaFuncSetAttribute(k_route, cudaFuncAttributeMaxDynamicSharedMemorySize, SEQ * 8);

    // weight converts (tiny)
    k_f2h<<<512, 256>>>(w_qkv_l, (__half*)p_wqkvh, DIM * 3 * HDH);
    k_f2h<<<512, 256>>>(w_out_l, (__half*)p_wolh, HDH * DIM);
    k_f2h<<<512, 256>>>(w_q_h,   (__half*)p_wqh,  DIM * HDH);
    k_f2h<<<512, 256>>>(w_kv_h,  (__half*)p_wkvh, DIM * DIM);
    k_f2h<<<512, 256>>>(w_out_h, (__half*)p_wohh, HDH * DIM);

    k_ln<<<NTOK, 256>>>(x, ln_g, ln_b, rt_q, rt_kv);
    k_init<<<(NTOK + 255) / 256, 256>>>();
    k_route<<<4, 1024, SEQ * 8>>>();
    k_gather<<<BATCH * (NQ + NKV), 256>>>(x, rms_g);

    // light path
    k_hgemm<<<dim3((3 * HDH) / 128, NTOK / 128), 256>>>((const __half*)p_xnh, (const __half*)p_wqkvh, (float*)p_qkv, NTOK, 3 * HDH, DIM);
    k_lattn<<<BATCH * HEADS * NWIN, 64>>>();
    k_hgemm<<<dim3(DIM / 128, NTOK / 128), 256>>>((const __half*)p_loh, (const __half*)p_wolh, out, NTOK, DIM, HDH);

    // heavy path
    k_hgemm<<<dim3(HDH / 128, (BATCH * NQ) / 128), 256>>>((const __half*)p_xqnh, (const __half*)p_wqh, (float*)p_qh, BATCH * NQ, HDH, DIM);
    k_hgemm<<<dim3(DIM / 128, (BATCH * NKV) / 128), 256>>>((const __half*)p_xkvnh, (const __half*)p_wkvh, (float*)p_kvh, BATCH * NKV, DIM, DIM);
    k_kvprep<<<1024, 256>>>(null_kv);
    k_hattn<<<BATCH * HEADS * (NQ / 64), 64>>>();
    k_hgemm<<<dim3(DIM / 128, (BATCH * NQ) / 128), 256>>>((const __half*)p_hoh, (const __half*)p_wohh, (float*)p_routed, BATCH * NQ, DIM, HDH);

    k_combine<<<NTOK, 256>>>(out, null_q);
}

// round 7
// speedup vs baseline: 4.2218x; 1.8854x over previous
#include <cuda_runtime.h>
#include <cuda_fp16.h>
#include <stdint.h>
#include <math.h>
#include <float.h>
#include <limits.h>

#define BATCH 2
#define SEQ   8192
#define DIM   1024
#define HEADS 8
#define DH    64
#define HDH   512
#define WIN   64
#define NWIN  128
#define NQ    1024
#define NKV   2048
#define NITER 50
#define NTOK  (BATCH*SEQ)
#define NKEY  (NKV+1)
#define NKEYP 2112          // padded to 64-key chunks

// ---------------- scratch ----------------
__device__ __half g_xnh[(size_t)NTOK*DIM];
__device__ float g_rms[NTOK];
__device__ float g_s[2][NTOK];
__device__ __half g_qkvh[(size_t)NTOK*(3*HDH)];
__device__ __half g_loh[(size_t)NTOK*HDH];
__device__ int   g_iq[BATCH][NQ];
__device__ float g_sq[BATCH][NQ];
__device__ int   g_ikv[BATCH][NKV];
__device__ float g_skv[BATCH][NKV];
__device__ int   g_qpos[NTOK];
__device__ __half g_xqnh[(size_t)BATCH*NQ*DIM];
__device__ __half g_xkvnh[(size_t)BATCH*NKV*DIM];
__device__ __half g_qhh[(size_t)BATCH*NQ*HDH];
__device__ float g_kvh[(size_t)BATCH*NKV*DIM];
__device__ __half g_khh[(size_t)BATCH*HEADS*NKEYP*DH];
__device__ __half g_vhh[(size_t)BATCH*HEADS*NKEYP*DH];
__device__ __half g_hoh[(size_t)BATCH*NQ*HDH];
__device__ float g_routed[(size_t)BATCH*NQ*DIM];
// fp16 weights
__device__ __half g_wqkvh[(size_t)DIM*3*HDH];
__device__ __half g_wolh[(size_t)HDH*DIM];
__device__ __half g_wqh[(size_t)DIM*HDH];
__device__ __half g_wkvh[(size_t)DIM*DIM];
__device__ __half g_wohh[(size_t)HDH*DIM];

// ---------------- asm helpers ----------------
__device__ __forceinline__ unsigned saddr(const void* p) {
    return (unsigned)__cvta_generic_to_shared(p);
}
__device__ __forceinline__ void cp16(unsigned dst, const void* src) {
    asm volatile("cp.async.cg.shared.global [%0], [%1], 16;" :: "r"(dst), "l"(src));
}
__device__ __forceinline__ void ldsm_x4(unsigned* r, unsigned a) {
    asm volatile("ldmatrix.sync.aligned.m8n8.x4.shared.b16 {%0,%1,%2,%3}, [%4];"
        : "=r"(r[0]), "=r"(r[1]), "=r"(r[2]), "=r"(r[3]) : "r"(a));
}
__device__ __forceinline__ void ldsm_x2(unsigned* r, unsigned a) {
    asm volatile("ldmatrix.sync.aligned.m8n8.x2.shared.b16 {%0,%1}, [%2];"
        : "=r"(r[0]), "=r"(r[1]) : "r"(a));
}
__device__ __forceinline__ void ldsm_x2t(unsigned* r, unsigned a) {
    asm volatile("ldmatrix.sync.aligned.m8n8.x2.trans.shared.b16 {%0,%1}, [%2];"
        : "=r"(r[0]), "=r"(r[1]) : "r"(a));
}
__device__ __forceinline__ void mma16816(float* d, const unsigned* a, const unsigned* b) {
    asm volatile("mma.sync.aligned.m16n8k16.row.col.f32.f16.f16.f32 "
        "{%0,%1,%2,%3}, {%4,%5,%6,%7}, {%8,%9}, {%0,%1,%2,%3};"
        : "+f"(d[0]), "+f"(d[1]), "+f"(d[2]), "+f"(d[3])
        : "r"(a[0]), "r"(a[1]), "r"(a[2]), "r"(a[3]), "r"(b[0]), "r"(b[1]));
}
__device__ __forceinline__ unsigned h2pack(float x, float y) {
    __half2 t = __floats2half2_rn(x, y);
    return *(unsigned*)&t;
}

// ---------------- reductions ----------------
__device__ __forceinline__ float bsum256(float v, float* sh) {
    int lane = threadIdx.x & 31, w = threadIdx.x >> 5;
    #pragma unroll
    for (int o = 16; o; o >>= 1) v += __shfl_xor_sync(0xffffffffu, v, o);
    __syncthreads();
    if (lane == 0) sh[w] = v;
    __syncthreads();
    float r = sh[0];
    #pragma unroll
    for (int i = 1; i < 8; i++) r += sh[i];
    return r;
}
__device__ __forceinline__ float bsum1024(float v, float* sh) {
    int lane = threadIdx.x & 31, w = threadIdx.x >> 5;
    #pragma unroll
    for (int o = 16; o; o >>= 1) v += __shfl_xor_sync(0xffffffffu, v, o);
    __syncthreads();
    if (lane == 0) sh[w] = v;
    __syncthreads();
    float r = sh[0];
    #pragma unroll
    for (int i = 1; i < 32; i++) r += sh[i];
    return r;
}
__device__ __forceinline__ float bmax1024(float v, float* sh) {
    int lane = threadIdx.x & 31, w = threadIdx.x >> 5;
    #pragma unroll
    for (int o = 16; o; o >>= 1) v = fmaxf(v, __shfl_xor_sync(0xffffffffu, v, o));
    __syncthreads();
    if (lane == 0) sh[w] = v;
    __syncthreads();
    float r = sh[0];
    #pragma unroll
    for (int i = 1; i < 32; i++) r = fmaxf(r, sh[i]);
    return r;
}

// ---------------- 1. layernorm + routing dots + qpos init ----------------
__global__ __launch_bounds__(256) void k_ln(const float* __restrict__ x,
        const float* __restrict__ ln_g, const float* __restrict__ ln_b,
        const float* __restrict__ rt_q, const float* __restrict__ rt_kv) {
    __shared__ float sh[32];
    __shared__ float s_mean, s_inv;
    int row = blockIdx.x;
    const float* xr = x + (size_t)row * DIM;
    int tid = threadIdx.x;
    float v[4], s = 0.f, ss = 0.f, dq = 0.f, dk = 0.f;
    #pragma unroll
    for (int u = 0; u < 4; u++) {
        int i = tid + 256 * u;
        float t = xr[i];
        v[u] = t; s += t; ss += t * t; dq += t * rt_q[i]; dk += t * rt_kv[i];
    }
    s  = bsum256(s, sh);
    ss = bsum256(ss, sh);
    dq = bsum256(dq, sh);
    dk = bsum256(dk, sh);
    if (tid == 0) {
        float mean = s * (1.0f / DIM);
        float var  = ss * (1.0f / DIM) - mean * mean;
        s_mean = mean;
        s_inv  = 1.0f / sqrtf(var + 1e-5f);
        g_rms[row] = 32.0f / fmaxf(sqrtf(ss), 1e-12f);
        g_s[0][row] = dq;
        g_s[1][row] = dk;
        g_qpos[row] = -1;
    }
    __syncthreads();
    float mean = s_mean, inv = s_inv;
    #pragma unroll
    for (int u = 0; u < 4; u++) {
        int i = tid + 256 * u;
        g_xnh[(size_t)row * DIM + i] = __float2half((v[u] - mean) * inv * ln_g[i] + ln_b[i]);
    }
}

// ---------------- 2. all weight converts in one kernel ----------------
#define NW1 (DIM*3*HDH)
#define NW2 (HDH*DIM)
#define NW3 (DIM*HDH)
#define NW4 (DIM*DIM)
#define NW5 (HDH*DIM)
__global__ void k_f2h_all(const float* w1, const float* w2, const float* w3,
                          const float* w4, const float* w5) {
    int total = NW1 + NW2 + NW3 + NW4 + NW5;
    for (int i = blockIdx.x * blockDim.x + threadIdx.x; i < total; i += gridDim.x * blockDim.x) {
        int j = i;
        if (j < NW1) { g_wqkvh[j] = __float2half(w1[j]); continue; } j -= NW1;
        if (j < NW2) { g_wolh[j]  = __float2half(w2[j]); continue; } j -= NW2;
        if (j < NW3) { g_wqh[j]   = __float2half(w3[j]); continue; } j -= NW3;
        if (j < NW4) { g_wkvh[j]  = __float2half(w4[j]); continue; } j -= NW4;
        g_wohh[j] = __float2half(w5[j]);
    }
}

// ---------------- 3. coor_descent + exact-tie-break top-k (bitonic) ----------------
__global__ __launch_bounds__(1024) void k_route() {
    extern __shared__ unsigned long long keys[];
    __shared__ float sh[32];
    int tid = threadIdx.x;
    int b = blockIdx.x >> 1, route = blockIdx.x & 1;
    const float* sp = g_s[route] + b * SEQ;
    float s[8], bb[8];
    #pragma unroll
    for (int u = 0; u < 8; u++) { s[u] = sp[tid + 1024 * u]; bb[u] = -s[u]; }
    float logk = logf(route ? 2304.0f : 1152.0f);
    float a = 0.0f;
    for (int it = 0; it < NITER; it++) {
        float lm = -FLT_MAX;
        #pragma unroll
        for (int u = 0; u < 8; u++) lm = fmaxf(lm, s[u] + bb[u]);
        float m = bmax1024(lm, sh);
        float ls = 0.0f;
        #pragma unroll
        for (int u = 0; u < 8; u++) ls += expf(s[u] + bb[u] - m);
        float sum = bsum1024(ls, sh);
        a = logk - (logf(sum) + m);
        #pragma unroll
        for (int u = 0; u < 8; u++) bb[u] = -fmaxf(s[u] + a, 0.0f);
    }
    #pragma unroll
    for (int u = 0; u < 8; u++) {
        int idx = tid + 1024 * u;
        float sc = expf(s[u] + a + bb[u]);
        keys[idx] = ((unsigned long long)__float_as_uint(sc) << 32)
                  | (unsigned)(SEQ - 1 - idx);
    }
    __syncthreads();
    for (int k2 = 2; k2 <= SEQ; k2 <<= 1) {
        for (int j = k2 >> 1; j > 0; j >>= 1) {
            #pragma unroll
            for (int w = 0; w < 8; w++) {
                int i = tid + 1024 * w;
                int ixj = i ^ j;
                if (ixj > i) {
                    unsigned long long A = keys[i], B = keys[ixj];
                    bool sw = ((i & k2) == 0) ? (A < B) : (A > B);
                    if (sw) { keys[i] = B; keys[ixj] = A; }
                }
            }
            __syncthreads();
        }
    }
    int N = route ? NKV : NQ;
    for (int i = tid; i < N; i += 1024) {
        unsigned long long kk = keys[i];
        int idx = (SEQ - 1) - (int)(unsigned)(kk & 0xffffffffu);
        float sc = __uint_as_float((unsigned)(kk >> 32));
        float sel = sc + (1.0f - sc);
        if (route) { g_ikv[b][i] = idx; g_skv[b][i] = sel; }
        else       { g_iq[b][i] = idx;  g_sq[b][i] = sel; g_qpos[b * SEQ + idx] = i; }
    }
}

// ---------------- 4. gather + rmsnorm (fp16 out) ----------------
__global__ __launch_bounds__(256) void k_gather(const float* __restrict__ x,
                                                const float* __restrict__ rms_g) {
    int r = blockIdx.x, tid = threadIdx.x;
    int b, tok; __half* dst;
    if (r < BATCH * NQ) { b = r / NQ; tok = g_iq[b][r % NQ]; dst = g_xqnh + (size_t)r * DIM; }
    else { int r2 = r - BATCH * NQ; b = r2 / NKV; tok = g_ikv[b][r2 % NKV]; dst = g_xkvnh + (size_t)r2 * DIM; }
    const float* src = x + ((size_t)(b * SEQ) + tok) * DIM;
    float sc = g_rms[b * SEQ + tok];
    for (int i = tid; i < DIM; i += 256) dst[i] = __float2half(src[i] * sc * rms_g[i]);
}

// ---------------- 5. fp16 tensor-core GEMM, templated output ----------------
template <typename OutT>
__global__ __launch_bounds__(256) void k_hgemm(const __half* __restrict__ A,
        const __half* __restrict__ B, OutT* __restrict__ C, int M, int N, int K) {
    __shared__ __half As[2][128 * 40];
    __shared__ __half Bs[2][32 * 136];
    int tid = threadIdx.x, lane = tid & 31, wid = tid >> 5;
    int wm = (wid & 1) * 64, wn = (wid >> 1) * 32;
    int arow = tid >> 2, acol = (tid & 3) * 8;
    int brow = tid >> 4, bcol = (tid & 15) * 8;
    const __half* Ag = A + (size_t)(blockIdx.y * 128) * K;
    const __half* Bg = B + blockIdx.x * 128;
    float acc[4][4][4];
    #pragma unroll
    for (int mt = 0; mt < 4; mt++)
        #pragma unroll
        for (int nt = 0; nt < 4; nt++)
            #pragma unroll
            for (int i = 0; i < 4; i++) acc[mt][nt][i] = 0.0f;
    {
        const __half* a0 = Ag + (size_t)arow * K + acol;
        cp16(saddr(&As[0][arow * 40 + acol]), a0);
        cp16(saddr(&As[0][(arow + 64) * 40 + acol]), a0 + (size_t)64 * K);
        const __half* b0 = Bg + (size_t)brow * N + bcol;
        cp16(saddr(&Bs[0][brow * 136 + bcol]), b0);
        cp16(saddr(&Bs[0][(brow + 16) * 136 + bcol]), b0 + (size_t)16 * N);
        asm volatile("cp.async.commit_group;");
    }
    int nstage = K >> 5;
    for (int s = 0; s < nstage; s++) {
        asm volatile("cp.async.wait_group 0;");
        __syncthreads();
        if (s + 1 < nstage) {
            int k0 = (s + 1) << 5;
            int st = (s + 1) & 1;
            const __half* a0 = Ag + (size_t)arow * K + k0 + acol;
            cp16(saddr(&As[st][arow * 40 + acol]), a0);
            cp16(saddr(&As[st][(arow + 64) * 40 + acol]), a0 + (size_t)64 * K);
            const __half* b0 = Bg + (size_t)(k0 + brow) * N + bcol;
            cp16(saddr(&Bs[st][brow * 136 + bcol]), b0);
            cp16(saddr(&Bs[st][(brow + 16) * 136 + bcol]), b0 + (size_t)16 * N);
            asm volatile("cp.async.commit_group;");
        }
        int cur = s & 1;
        #pragma unroll
        for (int kk = 0; kk < 32; kk += 16) {
            unsigned af[4][4], bf[4][2];
            #pragma unroll
            for (int mt = 0; mt < 4; mt++) {
                int row = wm + mt * 16 + (lane & 15);
                int col = kk + (lane >> 4) * 8;
                ldsm_x4(af[mt], saddr(&As[cur][row * 40 + col]));
            }
            #pragma unroll
            for (int nt = 0; nt < 4; nt++) {
                int row = kk + (lane & 15);
                ldsm_x2t(bf[nt], saddr(&Bs[cur][row * 136 + wn + nt * 8]));
            }
            #pragma unroll
            for (int mt = 0; mt < 4; mt++)
                #pragma unroll
                for (int nt = 0; nt < 4; nt++)
                    mma16816(acc[mt][nt], af[mt], bf[nt]);
        }
    }
    #pragma unroll
    for (int mt = 0; mt < 4; mt++) {
        int r = blockIdx.y * 128 + wm + mt * 16 + (lane >> 2);
        #pragma unroll
        for (int nt = 0; nt < 4; nt++) {
            int c = blockIdx.x * 128 + wn + nt * 8 + (lane & 3) * 2;
            if (sizeof(OutT) == 4) {
                *(float2*)((float*)C + (size_t)r * N + c)       = make_float2(acc[mt][nt][0], acc[mt][nt][1]);
                *(float2*)((float*)C + (size_t)(r + 8) * N + c) = make_float2(acc[mt][nt][2], acc[mt][nt][3]);
            } else {
                *(unsigned*)((__half*)C + (size_t)r * N + c)       = h2pack(acc[mt][nt][0], acc[mt][nt][1]);
                *(unsigned*)((__half*)C + (size_t)(r + 8) * N + c) = h2pack(acc[mt][nt][2], acc[mt][nt][3]);
            }
        }
    }
}

// ---------------- flash warp core: one 16-key block ----------------
__device__ __forceinline__ void flash_kb(const __half* sK, const __half* sV,
        int kb, int gkey, int firstInvalid,
        const unsigned (&af)[4][4], float (&o)[8][4], float (&m)[2], float (&l)[2], int lane) {
    float a0[4] = {0.f,0.f,0.f,0.f}, a1[4] = {0.f,0.f,0.f,0.f};
    #pragma unroll
    for (int kc = 0; kc < 4; kc++) {
        unsigned b0[2], b1[2];
        int r = lane & 7, cc = kc * 16 + ((lane >> 3) & 1) * 8;
        ldsm_x2(b0, saddr(&sK[(kb + r) * 72 + cc]));
        ldsm_x2(b1, saddr(&sK[(kb + 8 + r) * 72 + cc]));
        mma16816(a0, af[kc], b0);
        mma16816(a1, af[kc], b1);
    }
    #pragma unroll
    for (int i = 0; i < 4; i++) { a0[i] *= 0.125f; a1[i] *= 0.125f; }
    if (gkey + 16 > firstInvalid) {
        int c0 = gkey + ((lane & 3) << 1);
        if (c0     >= firstInvalid) { a0[0] = -1e30f; a0[2] = -1e30f; }
        if (c0 + 1 >= firstInvalid) { a0[1] = -1e30f; a0[3] = -1e30f; }
        if (c0 + 8 >= firstInvalid) { a1[0] = -1e30f; a1[2] = -1e30f; }
        if (c0 + 9 >= firstInvalid) { a1[1] = -1e30f; a1[3] = -1e30f; }
    }
    float mx0 = fmaxf(fmaxf(a0[0], a0[1]), fmaxf(a1[0], a1[1]));
    float mx1 = fmaxf(fmaxf(a0[2], a0[3]), fmaxf(a1[2], a1[3]));
    mx0 = fmaxf(mx0, __shfl_xor_sync(0xffffffffu, mx0, 1));
    mx0 = fmaxf(mx0, __shfl_xor_sync(0xffffffffu, mx0, 2));
    mx1 = fmaxf(mx1, __shfl_xor_sync(0xffffffffu, mx1, 1));
    mx1 = fmaxf(mx1, __shfl_xor_sync(0xffffffffu, mx1, 2));
    float nm0 = fmaxf(m[0], mx0), nm1 = fmaxf(m[1], mx1);
    float s0 = __expf(m[0] - nm0), s1 = __expf(m[1] - nm1);
    m[0] = nm0; m[1] = nm1;
    float p00 = __expf(a0[0] - nm0), p01 = __expf(a0[1] - nm0);
    float p02 = __expf(a1[0] - nm0), p03 = __expf(a1[1] - nm0);
    float p10 = __expf(a0[2] - nm1), p11 = __expf(a0[3] - nm1);
    float p12 = __expf(a1[2] - nm1), p13 = __expf(a1[3] - nm1);
    l[0] = l[0] * s0 + (p00 + p01 + p02 + p03);
    l[1] = l[1] * s1 + (p10 + p11 + p12 + p13);
    unsigned ap[4];
    ap[0] = h2pack(p00, p01);
    ap[1] = h2pack(p10, p11);
    ap[2] = h2pack(p02, p03);
    ap[3] = h2pack(p12, p13);
    #pragma unroll
    for (int nt = 0; nt < 8; nt++) {
        unsigned bv[2];
        ldsm_x2t(bv, saddr(&sV[(kb + (lane & 15)) * 72 + nt * 8]));
        o[nt][0] *= s0; o[nt][1] *= s0; o[nt][2] *= s1; o[nt][3] *= s1;
        mma16816(o[nt], ap, bv);
    }
}

// ---------------- 6. light windowed attention (tensor core) ----------------
__global__ __launch_bounds__(128) void k_flash_light() {
    __shared__ __half sQ[64 * 72], sK[64 * 72], sV[64 * 72];
    int idx = blockIdx.x;
    int w = idx & (NWIN - 1), h = (idx >> 7) & 7, b = idx >> 10;
    int tid = threadIdx.x, lane = tid & 31, warp = tid >> 5;
    const __half* qb_ = g_qkvh + (size_t)(b * SEQ + w * 64) * 1536 + h * 64;
    for (int i = tid; i < 64 * 8; i += 128) {
        int r = i >> 3, c = (i & 7) * 8;
        *(float4*)&sQ[r * 72 + c] = *(const float4*)(qb_ + (size_t)r * 1536 + c);
    }
    __syncthreads();
    unsigned af[4][4];
    int q0w = warp * 16;
    #pragma unroll
    for (int kc = 0; kc < 4; kc++)
        ldsm_x4(af[kc], saddr(&sQ[(q0w + (lane & 15)) * 72 + kc * 16 + ((lane >> 4) & 1) * 8]));
    float o[8][4];
    #pragma unroll
    for (int nt = 0; nt < 8; nt++)
        #pragma unroll
        for (int i = 0; i < 4; i++) o[nt][i] = 0.0f;
    float m[2] = {-1e30f, -1e30f}, l[2] = {0.0f, 0.0f};
    for (int kw = w - 1; kw <= w + 1; kw++) {
        if (kw < 0 || kw >= NWIN) continue;
        __syncthreads();
        const __half* kb_ = g_qkvh + (size_t)(b * SEQ + kw * 64) * 1536 + 512 + h * 64;
        const __half* vb_ = kb_ + 512;
        for (int i = tid; i < 64 * 8; i += 128) {
            int r = i >> 3, c = (i & 7) * 8;
            *(float4*)&sK[r * 72 + c] = *(const float4*)(kb_ + (size_t)r * 1536 + c);
            *(float4*)&sV[r * 72 + c] = *(const float4*)(vb_ + (size_t)r * 1536 + c);
        }
        __syncthreads();
        #pragma unroll
        for (int kb = 0; kb < 64; kb += 16)
            flash_kb(sK, sV, kb, 0, INT_MAX, af, o, m, l, lane);
    }
    l[0] += __shfl_xor_sync(0xffffffffu, l[0], 1);
    l[0] += __shfl_xor_sync(0xffffffffu, l[0], 2);
    l[1] += __shfl_xor_sync(0xffffffffu, l[1], 1);
    l[1] += __shfl_xor_sync(0xffffffffu, l[1], 2);
    float inv0 = 1.0f / l[0], inv1 = 1.0f / l[1];
    int r0 = b * SEQ + w * 64 + q0w + (lane >> 2);
    #pragma unroll
    for (int nt = 0; nt < 8; nt++) {
        int c = h * 64 + nt * 8 + (lane & 3) * 2;
        *(unsigned*)&g_loh[(size_t)r0 * 512 + c]       = h2pack(o[nt][0] * inv0, o[nt][1] * inv0);
        *(unsigned*)&g_loh[(size_t)(r0 + 8) * 512 + c] = h2pack(o[nt][2] * inv1, o[nt][3] * inv1);
    }
}

// ---------------- 7. build heavy K/V (fp16, padded) ----------------
__global__ void k_kvprep(const float* __restrict__ null_kv) {
    const int total = BATCH * HEADS * NKEYP * DH;
    for (int i = blockIdx.x * blockDim.x + threadIdx.x; i < total; i += gridDim.x * blockDim.x) {
        int d = i & (DH - 1);
        int j = (i >> 6) % NKEYP;
        int h = (i / (DH * NKEYP)) % HEADS;
        int b = i / (DH * NKEYP * HEADS);
        float kv = 0.0f, vv = 0.0f;
        if (j == 0) {
            kv = null_kv[h * DH + d];
            vv = null_kv[HEADS * DH + h * DH + d];
        } else if (j < NKEY) {
            size_t rowo = ((size_t)(b * NKV + j - 1)) * DIM + h * 2 * DH;
            kv = g_kvh[rowo + d];
            vv = g_kvh[rowo + DH + d] * g_skv[b][j - 1];
        }
        g_khh[i] = __float2half(kv);
        g_vhh[i] = __float2half(vv);
    }
}

// ---------------- 8. heavy attention (tensor core flash) ----------------
__global__ __launch_bounds__(128) void k_flash_heavy() {
    __shared__ __half sQ[64 * 72], sK[64 * 72], sV[64 * 72];
    int idx = blockIdx.x;
    int qc = idx & 15, h = (idx >> 4) & 7, b = idx >> 7;
    int tid = threadIdx.x, lane = tid & 31, warp = tid >> 5;
    const __half* qb_ = g_qhh + (size_t)(b * NQ + qc * 64) * 512 + h * 64;
    for (int i = tid; i < 64 * 8; i += 128) {
        int r = i >> 3, c = (i & 7) * 8;
        *(float4*)&sQ[r * 72 + c] = *(const float4*)(qb_ + (size_t)r * 512 + c);
    }
    __syncthreads();
    unsigned af[4][4];
    int q0w = warp * 16;
    #pragma unroll
    for (int kc = 0; kc < 4; kc++)
        ldsm_x4(af[kc], saddr(&sQ[(q0w + (lane & 15)) * 72 + kc * 16 + ((lane >> 4) & 1) * 8]));
    float o[8][4];
    #pragma unroll
    for (int nt = 0; nt < 8; nt++)
        #pragma unroll
        for (int i = 0; i < 4; i++) o[nt][i] = 0.0f;
    float m[2] = {-1e30f, -1e30f}, l[2] = {0.0f, 0.0f};
    const __half* kbase = g_khh + (size_t)(b * HEADS + h) * NKEYP * DH;
    const __half* vbase = g_vhh + (size_t)(b * HEADS + h) * NKEYP * DH;
    for (int chunk = 0; chunk < NKEYP; chunk += 64) {
        __syncthreads();
        for (int i = tid; i < 64 * 8; i += 128) {
            int r = i >> 3, c = (i & 7) * 8;
            *(float4*)&sK[r * 72 + c] = *(const float4*)(kbase + (size_t)(chunk + r) * 64 + c);
            *(float4*)&sV[r * 72 + c] = *(const float4*)(vbase + (size_t)(chunk + r) * 64 + c);
        }
        __syncthreads();
        int nkb = NKEY - chunk;
        nkb = nkb > 64 ? 64 : ((nkb + 15) & ~15);
        for (int kb = 0; kb < nkb; kb += 16)
            flash_kb(sK, sV, kb, chunk + kb, NKEY, af, o, m, l, lane);
    }
    l[0] += __shfl_xor_sync(0xffffffffu, l[0], 1);
    l[0] += __shfl_xor_sync(0xffffffffu, l[0], 2);
    l[1] += __shfl_xor_sync(0xffffffffu, l[1], 1);
    l[1] += __shfl_xor_sync(0xffffffffu, l[1], 2);
    float inv0 = 1.0f / l[0], inv1 = 1.0f / l[1];
    int r0 = b * NQ + qc * 64 + q0w + (lane >> 2);
    #pragma unroll
    for (int nt = 0; nt < 8; nt++) {
        int c = h * 64 + nt * 8 + (lane & 3) * 2;
        *(unsigned*)&g_hoh[(size_t)r0 * 512 + c]       = h2pack(o[nt][0] * inv0, o[nt][1] * inv0);
        *(unsigned*)&g_hoh[(size_t)(r0 + 8) * 512 + c] = h2pack(o[nt][2] * inv1, o[nt][3] * inv1);
    }
}

// ---------------- 9. combine ----------------
__global__ __launch_bounds__(256) void k_combine(float* __restrict__ out,
                                                 const float* __restrict__ null_q) {
    int row = blockIdx.x, tid = threadIdx.x;
    int pos = g_qpos[row];
    float* orow = out + (size_t)row * DIM;
    if (pos >= 0) {
        int b = row / SEQ;
        float sq = g_sq[b][pos];
        const float* rr = g_routed + ((size_t)(b * NQ + pos)) * DIM;
        for (int i = tid; i < DIM; i += 256) orow[i] += rr[i] * sq;
    } else {
        for (int i = tid; i < DIM; i += 256) orow[i] += null_q[i];
    }
}

// ---------------- launcher ----------------
extern "C" void kernel_launch(void* const* d_in, const int* in_sizes, int n_in,
                              void* d_out, int out_size) {
    const float* x       = (const float*)d_in[0];
    const float* ln_g    = (const float*)d_in[1];
    const float* ln_b    = (const float*)d_in[2];
    const float* w_qkv_l = (const float*)d_in[3];
    const float* w_out_l = (const float*)d_in[4];
    const float* null_q  = (const float*)d_in[5];
    const float* rt_q    = (const float*)d_in[6];
    const float* rt_kv   = (const float*)d_in[7];
    const float* rms_g   = (const float*)d_in[8];
    const float* w_q_h   = (const float*)d_in[9];
    const float* w_kv_h  = (const float*)d_in[10];
    const float* null_kv = (const float*)d_in[11];
    const float* w_out_h = (const float*)d_in[12];
    float* out = (float*)d_out;

    void *p_xnh, *p_qkvh, *p_loh, *p_xqnh, *p_xkvnh, *p_qhh, *p_kvh, *p_hoh, *p_routed;
    void *p_wqkvh, *p_wolh, *p_wqh, *p_wkvh, *p_wohh;
    cudaGetSymbolAddress(&p_xnh, g_xnh);
    cudaGetSymbolAddress(&p_qkvh, g_qkvh);
    cudaGetSymbolAddress(&p_loh, g_loh);
    cudaGetSymbolAddress(&p_xqnh, g_xqnh);
    cudaGetSymbolAddress(&p_xkvnh, g_xkvnh);
    cudaGetSymbolAddress(&p_qhh, g_qhh);
    cudaGetSymbolAddress(&p_kvh, g_kvh);
    cudaGetSymbolAddress(&p_hoh, g_hoh);
    cudaGetSymbolAddress(&p_routed, g_routed);
    cudaGetSymbolAddress(&p_wqkvh, g_wqkvh);
    cudaGetSymbolAddress(&p_wolh, g_wolh);
    cudaGetSymbolAddress(&p_wqh, g_wqh);
    cudaGetSymbolAddress(&p_wkvh, g_wkvh);
    cudaGetSymbolAddress(&p_wohh, g_wohh);

    cudaFuncSetAttribute(k_route, cudaFuncAttributeMaxDynamicSharedMemorySize, SEQ * 8);

    k_f2h_all<<<512, 256>>>(w_qkv_l, w_out_l, w_q_h, w_kv_h, w_out_h);
    k_ln<<<NTOK, 256>>>(x, ln_g, ln_b, rt_q, rt_kv);
    k_route<<<4, 1024, SEQ * 8>>>();
    k_gather<<<BATCH * (NQ + NKV), 256>>>(x, rms_g);

    // light path
    k_hgemm<__half><<<dim3((3 * HDH) / 128, NTOK / 128), 256>>>((const __half*)p_xnh, (const __half*)p_wqkvh, (__half*)p_qkvh, NTOK, 3 * HDH, DIM);
    k_flash_light<<<BATCH * HEADS * NWIN, 128>>>();
    k_hgemm<float><<<dim3(DIM / 128, NTOK / 128), 256>>>((const __half*)p_loh, (const __half*)p_wolh, out, NTOK, DIM, HDH);

    // heavy path
    k_hgemm<__half><<<dim3(HDH / 128, (BATCH * NQ) / 128), 256>>>((const __half*)p_xqnh, (const __half*)p_wqh, (__half*)p_qhh, BATCH * NQ, HDH, DIM);
    k_hgemm<float><<<dim3(DIM / 128, (BATCH * NKV) / 128), 256>>>((const __half*)p_xkvnh, (const __half*)p_wkvh, (float*)p_kvh, BATCH * NKV, DIM, DIM);
    k_kvprep<<<1024, 256>>>(null_kv);
    k_flash_heavy<<<BATCH * HEADS * (NQ / 64), 128>>>();
    k_hgemm<float><<<dim3(DIM / 128, (BATCH * NQ) / 128), 256>>>((const __half*)p_hoh, (const __half*)p_wohh, (float*)p_routed, BATCH * NQ, DIM, HDH);

    k_combine<<<NTOK, 256>>>(out, null_q);
}